// round 6
// baseline (speedup 1.0000x reference)
#include <cuda_runtime.h>
#include <cstdint>
#include <cstddef>

// ---------------- problem dims ----------------
#define B_ROWS 16384
#define D_DIM  4096
#define H_DIM  2048
#define E_DIM  64
#define TEMP   0.8f

// out (float32): [0,32768) weights, [32768,65536) indices (as float), [65536] uncertainty

// ---------------- device scratch ----------------
__device__ float g_h[(size_t)B_ROWS * H_DIM];     // 128 MB hidden activations
__device__ float g_part[B_ROWS / 128];            // per-CTA entropy partials

// ---------------- helpers ----------------
__device__ __forceinline__ uint32_t smem_u32(const void* p) {
    uint32_t a;
    asm("{ .reg .u64 t; cvta.to.shared.u64 t, %1; cvt.u32.u64 %0, t; }" : "=r"(a) : "l"(p));
    return a;
}
__device__ __forceinline__ uint32_t tf32_of(float x) {
    uint32_t u; asm("cvt.rna.tf32.f32 %0, %1;" : "=r"(u) : "f"(x));
    return u;
}
// SW128-style swizzle on (row, byte-in-row) with 128B rows (32 f32 per k-chunk row)
#define SWIZ(r, cb) ((((r) * 128 + (cb))) ^ (((r) & 7) << 4))

#define CP_ASYNC16(saddr, gptr) \
    asm volatile("cp.async.cg.shared.global [%0], [%1], 16;" :: "r"(saddr), "l"(gptr) : "memory")
#define CP_COMMIT() asm volatile("cp.async.commit_group;" ::: "memory")
#define CP_WAIT(n)  asm volatile("cp.async.wait_group %0;" :: "n"(n) : "memory")

__device__ __forceinline__ void mma_tf32(float* d, const uint32_t* a, const uint32_t* b) {
    asm volatile(
        "mma.sync.aligned.m16n8k8.row.col.f32.tf32.tf32.f32 "
        "{%0,%1,%2,%3}, {%4,%5,%6,%7}, {%8,%9}, {%0,%1,%2,%3};"
        : "+f"(d[0]), "+f"(d[1]), "+f"(d[2]), "+f"(d[3])
        : "r"(a[0]), "r"(a[1]), "r"(a[2]), "r"(a[3]), "r"(b[0]), "r"(b[1]));
}

// split a raw fp32 fragment into tf32 hi + tf32 lo
__device__ __forceinline__ void split4(const float* raw, uint32_t* hi, uint32_t* lo) {
#pragma unroll
    for (int j = 0; j < 4; j++) {
        uint32_t h = tf32_of(raw[j]);
        hi[j] = h;
        lo[j] = tf32_of(raw[j] - __uint_as_float(h));
    }
}
__device__ __forceinline__ void split2(const float* raw, uint32_t* hi, uint32_t* lo) {
#pragma unroll
    for (int j = 0; j < 2; j++) {
        uint32_t h = tf32_of(raw[j]);
        hi[j] = h;
        lo[j] = tf32_of(raw[j] - __uint_as_float(h));
    }
}

// ============================================================================
// GEMM1: h = relu(x @ W1^T + b1)
// 128x128 CTA tile, K-chunk 32, 3-stage cp.async pipeline.
// 4 warps, each computes a 64x64 warp tile via m16n8k8 tf32 mma (3x emulation).
// SMEM stage: A 16KB (128 rows x 32 f32, swizzled) | B 16KB. 3 stages = 96KB.
// ============================================================================
#define G1_STAGE 32768
#define G1_SMEM  (3 * G1_STAGE)

__device__ __forceinline__ void g1_load(uint32_t stg_u, const float* __restrict__ x,
                                        const float* __restrict__ w1,
                                        int m0, int n0, int k0, int tid) {
#pragma unroll
    for (int t = 0; t < 8; t++) {            // A: 1024 float4
        const int q = tid + t * 128;
        const int row = q >> 3, c4 = q & 7;
        CP_ASYNC16(stg_u + SWIZ(row, c4 * 16),
                   x + (size_t)(m0 + row) * D_DIM + k0 + c4 * 4);
    }
#pragma unroll
    for (int t = 0; t < 8; t++) {            // B: 1024 float4 (128 n-rows)
        const int q = tid + t * 128;
        const int row = q >> 3, c4 = q & 7;
        CP_ASYNC16(stg_u + 16384 + SWIZ(row, c4 * 16),
                   w1 + (size_t)(n0 + row) * D_DIM + k0 + c4 * 4);
    }
}

__global__ void __launch_bounds__(128)
g1_kernel(const float* __restrict__ x, const float* __restrict__ w1,
          const float* __restrict__ b1) {
    extern __shared__ __align__(1024) char smem[];
    const int tid = threadIdx.x;
    const int wid = tid >> 5, lid = tid & 31;
    const int wm = wid >> 1, wn = wid & 1;       // 2x2 warp grid of 64x64 tiles
    const int m0 = (int)(blockIdx.x >> 4) * 128;
    const int n0 = (int)(blockIdx.x & 15) * 128; // n-fastest: x panel + W1 L2 reuse
    const uint32_t sb = smem_u32(smem);

    float acc[4][8][4];
#pragma unroll
    for (int a = 0; a < 4; a++)
#pragma unroll
        for (int b = 0; b < 8; b++)
#pragma unroll
            for (int c = 0; c < 4; c++) acc[a][b][c] = 0.0f;

    g1_load(sb, x, w1, m0, n0, 0, tid);  CP_COMMIT();
    g1_load(sb + G1_STAGE, x, w1, m0, n0, 32, tid);  CP_COMMIT();

    const int lr = lid >> 2;      // 0..7
    const int lc = lid & 3;       // 0..3

    for (int i = 0; i < 128; i++) {
        if (i + 2 < 128) g1_load(sb + ((i + 2) % 3) * G1_STAGE, x, w1, m0, n0, (i + 2) * 32, tid);
        CP_COMMIT();
        CP_WAIT(2);
        __syncthreads();
        const char* sA = smem + (i % 3) * G1_STAGE;
        const char* sB = sA + 16384;

#pragma unroll
        for (int ks = 0; ks < 4; ks++) {
            uint32_t ahi[4][4], alo[4][4], bhi[8][2], blo[8][2];
#pragma unroll
            for (int mt = 0; mt < 4; mt++) {
                const int r0 = wm * 64 + mt * 16 + lr;
                const int cb = (ks * 8 + lc) * 4;
                float raw[4];
                raw[0] = *(const float*)(sA + SWIZ(r0,     cb));
                raw[1] = *(const float*)(sA + SWIZ(r0 + 8, cb));
                raw[2] = *(const float*)(sA + SWIZ(r0,     cb + 16));
                raw[3] = *(const float*)(sA + SWIZ(r0 + 8, cb + 16));
                split4(raw, ahi[mt], alo[mt]);
            }
#pragma unroll
            for (int nt = 0; nt < 8; nt++) {
                const int rn = wn * 64 + nt * 8 + lr;
                const int cb = (ks * 8 + lc) * 4;
                float raw[2];
                raw[0] = *(const float*)(sB + SWIZ(rn, cb));
                raw[1] = *(const float*)(sB + SWIZ(rn, cb + 16));
                split2(raw, bhi[nt], blo[nt]);
            }
#pragma unroll
            for (int mt = 0; mt < 4; mt++)
#pragma unroll
                for (int nt = 0; nt < 8; nt++) {
                    mma_tf32(acc[mt][nt], ahi[mt], bhi[nt]);
                    mma_tf32(acc[mt][nt], ahi[mt], blo[nt]);
                    mma_tf32(acc[mt][nt], alo[mt], bhi[nt]);
                }
        }
        __syncthreads();
    }

    // epilogue: bias + relu -> g_h
#pragma unroll
    for (int mt = 0; mt < 4; mt++) {
        const int m = m0 + wm * 64 + mt * 16 + lr;
#pragma unroll
        for (int nt = 0; nt < 8; nt++) {
            const int n = n0 + wn * 64 + nt * 8 + 2 * lc;
            const float bb0 = __ldg(b1 + n), bb1 = __ldg(b1 + n + 1);
            float2 v0, v1;
            v0.x = fmaxf(acc[mt][nt][0] + bb0, 0.0f);
            v0.y = fmaxf(acc[mt][nt][1] + bb1, 0.0f);
            v1.x = fmaxf(acc[mt][nt][2] + bb0, 0.0f);
            v1.y = fmaxf(acc[mt][nt][3] + bb1, 0.0f);
            *(float2*)(g_h + (size_t)m * H_DIM + n) = v0;
            *(float2*)(g_h + (size_t)(m + 8) * H_DIM + n) = v1;
        }
    }
}

// ============================================================================
// GEMM2: logits = h @ W2^T + b2 (M=16384, N=64, K=2048), fused routing epilogue
// 128x64 CTA tile, 4 warps of 32x64. SMEM stage: A 16KB | B 8KB; 3 stages.
// ============================================================================
#define G2_STAGE 24576
#define G2_SMEM  (3 * G2_STAGE)

__device__ __forceinline__ void g2_load(uint32_t stg_u, const float* __restrict__ h,
                                        const float* __restrict__ w2,
                                        int m0, int k0, int tid) {
#pragma unroll
    for (int t = 0; t < 8; t++) {            // A: 1024 float4
        const int q = tid + t * 128;
        const int row = q >> 3, c4 = q & 7;
        CP_ASYNC16(stg_u + SWIZ(row, c4 * 16),
                   h + (size_t)(m0 + row) * H_DIM + k0 + c4 * 4);
    }
#pragma unroll
    for (int t = 0; t < 4; t++) {            // B: 512 float4 (64 expert rows)
        const int q = tid + t * 128;
        const int row = q >> 3, c4 = q & 7;
        CP_ASYNC16(stg_u + 16384 + SWIZ(row, c4 * 16),
                   w2 + (size_t)row * H_DIM + k0 + c4 * 4);
    }
}

__global__ void __launch_bounds__(128)
g2_kernel(const float* __restrict__ w2, const float* __restrict__ b2,
          float* __restrict__ out) {
    extern __shared__ __align__(1024) char smem[];
    const int tid = threadIdx.x;
    const int wid = tid >> 5, lid = tid & 31;
    const int m0 = (int)blockIdx.x * 128;
    const uint32_t sb = smem_u32(smem);
    const float* hsrc = g_h;

    float acc[2][8][4];
#pragma unroll
    for (int a = 0; a < 2; a++)
#pragma unroll
        for (int b = 0; b < 8; b++)
#pragma unroll
            for (int c = 0; c < 4; c++) acc[a][b][c] = 0.0f;

    g2_load(sb, hsrc, w2, m0, 0, tid);  CP_COMMIT();
    g2_load(sb + G2_STAGE, hsrc, w2, m0, 32, tid);  CP_COMMIT();

    const int lr = lid >> 2, lc = lid & 3;

    for (int i = 0; i < 64; i++) {
        if (i + 2 < 64) g2_load(sb + ((i + 2) % 3) * G2_STAGE, hsrc, w2, m0, (i + 2) * 32, tid);
        CP_COMMIT();
        CP_WAIT(2);
        __syncthreads();
        const char* sA = smem + (i % 3) * G2_STAGE;
        const char* sB = sA + 16384;

#pragma unroll
        for (int ks = 0; ks < 4; ks++) {
            uint32_t ahi[2][4], alo[2][4], bhi[8][2], blo[8][2];
#pragma unroll
            for (int mt = 0; mt < 2; mt++) {
                const int r0 = wid * 32 + mt * 16 + lr;
                const int cb = (ks * 8 + lc) * 4;
                float raw[4];
                raw[0] = *(const float*)(sA + SWIZ(r0,     cb));
                raw[1] = *(const float*)(sA + SWIZ(r0 + 8, cb));
                raw[2] = *(const float*)(sA + SWIZ(r0,     cb + 16));
                raw[3] = *(const float*)(sA + SWIZ(r0 + 8, cb + 16));
                split4(raw, ahi[mt], alo[mt]);
            }
#pragma unroll
            for (int nt = 0; nt < 8; nt++) {
                const int rn = nt * 8 + lr;
                const int cb = (ks * 8 + lc) * 4;
                float raw[2];
                raw[0] = *(const float*)(sB + SWIZ(rn, cb));
                raw[1] = *(const float*)(sB + SWIZ(rn, cb + 16));
                split2(raw, bhi[nt], blo[nt]);
            }
#pragma unroll
            for (int mt = 0; mt < 2; mt++)
#pragma unroll
                for (int nt = 0; nt < 8; nt++) {
                    mma_tf32(acc[mt][nt], ahi[mt], bhi[nt]);
                    mma_tf32(acc[mt][nt], ahi[mt], blo[nt]);
                    mma_tf32(acc[mt][nt], alo[mt], bhi[nt]);
                }
        }
        __syncthreads();
    }

    // ---- write logits (+bias) to smem, stride 65 to dodge bank conflicts ----
    __syncthreads();
    float* lg = (float*)smem;                       // 128 x 65 floats = 33.3KB < 72KB
#pragma unroll
    for (int mt = 0; mt < 2; mt++) {
        const int rr = wid * 32 + mt * 16 + lr;
#pragma unroll
        for (int nt = 0; nt < 8; nt++) {
            const int cc = nt * 8 + 2 * lc;
            const float bb0 = __ldg(b2 + cc), bb1 = __ldg(b2 + cc + 1);
            lg[rr * 65 + cc]           = acc[mt][nt][0] + bb0;
            lg[rr * 65 + cc + 1]       = acc[mt][nt][1] + bb1;
            lg[(rr + 8) * 65 + cc]     = acc[mt][nt][2] + bb0;
            lg[(rr + 8) * 65 + cc + 1] = acc[mt][nt][3] + bb1;
        }
    }
    __syncthreads();

    // ---- per-row routing: thread t owns row t ----
    float l[64];
#pragma unroll
    for (int j = 0; j < 64; j++) l[j] = lg[tid * 65 + j];

    float b1v = l[0], b2v = -3.4e38f;
    int i1 = 0, i2 = 0;
#pragma unroll
    for (int j = 1; j < 64; j++) {
        const float v = l[j];
        if (v > b1v)      { b2v = b1v; i2 = i1; b1v = v; i1 = j; }
        else if (v > b2v) { b2v = v; i2 = j; }
    }
    const float e2 = __expf((b2v - b1v) / TEMP);   // top-2 of temp-softmax, renormed
    const float w0 = 1.0f / (1.0f + e2);
    const float w1v = e2 / (1.0f + e2);

    float S = 0.0f;                                 // entropy of UN-scaled softmax
#pragma unroll
    for (int j = 0; j < 64; j++) S += expf(l[j] - b1v);
    const float invS = 1.0f / S;
    float ent = 0.0f;
#pragma unroll
    for (int j = 0; j < 64; j++) {
        const float p = expf(l[j] - b1v) * invS;
        ent -= p * logf(p + 1e-10f);
    }

    const int r = m0 + tid;
    out[2 * r + 0] = w0;
    out[2 * r + 1] = w1v;
    out[2 * B_ROWS + 2 * r + 0] = (float)i1;
    out[2 * B_ROWS + 2 * r + 1] = (float)i2;

    // deterministic per-CTA entropy partial
    float e = ent;
#pragma unroll
    for (int o = 16; o > 0; o >>= 1) e += __shfl_down_sync(0xffffffffu, e, o);
    __syncthreads();
    float* part = lg + 128 * 65;
    if ((tid & 31) == 0) part[wid] = e;
    __syncthreads();
    if (tid == 0) g_part[blockIdx.x] = part[0] + part[1] + part[2] + part[3];
}

// ---------------- finalize: deterministic mean entropy ----------------
__global__ void fin_kernel(float* __restrict__ out) {
    if (threadIdx.x == 0) {
        float s = 0.0f;
        for (int i = 0; i < B_ROWS / 128; i++) s += g_part[i];
        out[2 * B_ROWS * 2] = (s / (float)B_ROWS) / logf((float)E_DIM);
    }
}

// ---------------- launch ----------------
extern "C" void kernel_launch(void* const* d_in, const int* in_sizes, int n_in,
                              void* d_out, int out_size) {
    const float* x  = (const float*)d_in[0];
    const float* W1 = (const float*)d_in[1];
    const float* b1 = (const float*)d_in[2];
    const float* W2 = (const float*)d_in[3];
    const float* b2 = (const float*)d_in[4];
    float* out = (float*)d_out;
    (void)in_sizes; (void)n_in; (void)out_size;

    cudaFuncSetAttribute(g1_kernel, cudaFuncAttributeMaxDynamicSharedMemorySize, G1_SMEM);
    cudaFuncSetAttribute(g2_kernel, cudaFuncAttributeMaxDynamicSharedMemorySize, G2_SMEM);

    g1_kernel<<<(B_ROWS / 128) * (H_DIM / 128), 128, G1_SMEM>>>(x, W1, b1);  // 2048 CTAs
    g2_kernel<<<B_ROWS / 128, 128, G2_SMEM>>>(W2, b2, out);                  // 128 CTAs
    fin_kernel<<<1, 32>>>(out);
}

// round 7
// speedup vs baseline: 1.5984x; 1.5984x over previous
#include <cuda_runtime.h>
#include <cuda_fp16.h>
#include <cstdint>
#include <cstddef>

// ---------------- problem dims ----------------
#define B_ROWS 16384
#define D_DIM  4096
#define H_DIM  2048
#define E_DIM  64
#define TEMP   0.8f
#define LO_SCALE 2048.0f
#define LO_INV   4.8828125e-4f   // 1/2048

// out (float32): [0,32768) weights, [32768,65536) indices (as float), [65536] uncertainty

// ---------------- device scratch (split half planes) ----------------
__device__ __half g_xh[(size_t)B_ROWS * D_DIM];   // 134 MB
__device__ __half g_xl[(size_t)B_ROWS * D_DIM];
__device__ __half g_w1h[(size_t)H_DIM * D_DIM];   // 16.8 MB
__device__ __half g_w1l[(size_t)H_DIM * D_DIM];
__device__ __half g_w2h[(size_t)E_DIM * H_DIM];
__device__ __half g_w2l[(size_t)E_DIM * H_DIM];
__device__ __half g_hh[(size_t)B_ROWS * H_DIM];   // 67 MB
__device__ __half g_hl[(size_t)B_ROWS * H_DIM];
__device__ float  g_part[B_ROWS / 128];

// ---------------- helpers ----------------
__device__ __forceinline__ uint32_t smem_u32(const void* p) {
    uint32_t a;
    asm("{ .reg .u64 t; cvta.to.shared.u64 t, %1; cvt.u32.u64 %0, t; }" : "=r"(a) : "l"(p));
    return a;
}

#define CP_ASYNC16(saddr, gptr) \
    asm volatile("cp.async.cg.shared.global [%0], [%1], 16;" :: "r"(saddr), "l"(gptr) : "memory")
#define CP_COMMIT() asm volatile("cp.async.commit_group;" ::: "memory")
#define CP_WAIT(n)  asm volatile("cp.async.wait_group %0;" :: "n"(n) : "memory")

#define LDSM_X4(r0, r1, r2, r3, addr) \
    asm volatile("ldmatrix.sync.aligned.m8n8.x4.shared.b16 {%0,%1,%2,%3}, [%4];" \
                 : "=r"(r0), "=r"(r1), "=r"(r2), "=r"(r3) : "r"(addr))

__device__ __forceinline__ void mma16816(float* d, const uint32_t* a, const uint32_t* b) {
    asm volatile(
        "mma.sync.aligned.m16n8k16.row.col.f32.f16.f16.f32 "
        "{%0,%1,%2,%3}, {%4,%5,%6,%7}, {%8,%9}, {%0,%1,%2,%3};"
        : "+f"(d[0]), "+f"(d[1]), "+f"(d[2]), "+f"(d[3])
        : "r"(a[0]), "r"(a[1]), "r"(a[2]), "r"(a[3]), "r"(b[0]), "r"(b[1]));
}

// plane row = 32 halfs = 64B; 16B segs swizzled: seg' = seg ^ ((row>>1)&3)
__device__ __forceinline__ uint32_t plane_off(int row, int seg) {
    return (uint32_t)(row * 64 + ((seg ^ ((row >> 1) & 3)) << 4));
}

// ---------------- prepass: split fp32 -> (hi, lo*2048) fp16 planes ----------------
__global__ void split_kernel(const float* __restrict__ src, __half* __restrict__ hi,
                             __half* __restrict__ lo, int n4) {
    for (int i = blockIdx.x * blockDim.x + threadIdx.x; i < n4; i += gridDim.x * blockDim.x) {
        float4 v = ((const float4*)src)[i];
        __half h0 = __float2half_rn(v.x), h1 = __float2half_rn(v.y);
        __half h2 = __float2half_rn(v.z), h3 = __float2half_rn(v.w);
        __half l0 = __float2half_rn((v.x - __half2float(h0)) * LO_SCALE);
        __half l1 = __float2half_rn((v.y - __half2float(h1)) * LO_SCALE);
        __half l2 = __float2half_rn((v.z - __half2float(h2)) * LO_SCALE);
        __half l3 = __float2half_rn((v.w - __half2float(h3)) * LO_SCALE);
        ((__half2*)hi)[2 * i]     = __halves2half2(h0, h1);
        ((__half2*)hi)[2 * i + 1] = __halves2half2(h2, h3);
        ((__half2*)lo)[2 * i]     = __halves2half2(l0, l1);
        ((__half2*)lo)[2 * i + 1] = __halves2half2(l2, l3);
    }
}

// ============================================================================
// GEMM1: h = relu(x @ W1^T + b1). 128x128 CTA tile, K-chunk 32, 3-stage cp.async.
// 512 threads = 16 warps (4x4 grid), warp tile 32x32. fp16 3-term emulation.
// Stage: A_hi 8K | A_lo 8K | B_hi 8K | B_lo 8K = 32KB; 3 stages = 96KB.
// ============================================================================
#define G1_STAGE 32768
#define G1_SMEM  (3 * G1_STAGE)

__device__ __forceinline__ void g1_load(uint32_t stg, int m0, int n0, int k0, int tid) {
    const __half* aplane[2] = { g_xh,  g_xl };
    const __half* bplane[2] = { g_w1h, g_w1l };
#pragma unroll
    for (int t = 0; t < 2; t++) {              // A: 1024 cp (128 rows x 4 segs x 2 planes)
        const int q = tid + t * 512;
        const int pl = q >> 9, r = (q >> 2) & 127, seg = q & 3;
        CP_ASYNC16(stg + pl * 8192 + plane_off(r, seg),
                   aplane[pl] + (size_t)(m0 + r) * D_DIM + k0 + seg * 8);
    }
#pragma unroll
    for (int t = 0; t < 2; t++) {              // B: 1024 cp
        const int q = tid + t * 512;
        const int pl = q >> 9, r = (q >> 2) & 127, seg = q & 3;
        CP_ASYNC16(stg + 16384 + pl * 8192 + plane_off(r, seg),
                   bplane[pl] + (size_t)(n0 + r) * D_DIM + k0 + seg * 8);
    }
}

__global__ void __launch_bounds__(512)
g1_kernel(const float* __restrict__ b1) {
    extern __shared__ __align__(1024) char smem[];
    const int tid = threadIdx.x;
    const int wid = tid >> 5, lid = tid & 31;
    const int wm = wid >> 2, wn = wid & 3;        // 4x4 warp grid, 32x32 tiles
    const int m0 = (int)(blockIdx.x >> 4) * 128;
    const int n0 = (int)(blockIdx.x & 15) * 128;
    const uint32_t sb = smem_u32(smem);

    float accM[2][4][4], accC[2][4][4];
#pragma unroll
    for (int a = 0; a < 2; a++)
#pragma unroll
        for (int b = 0; b < 4; b++)
#pragma unroll
            for (int c = 0; c < 4; c++) { accM[a][b][c] = 0.0f; accC[a][b][c] = 0.0f; }

    // per-lane ldmatrix geometry (row parts invariant across mt/nt/kstep)
    const int ra  = wm * 32 + ((lid >> 3) & 1) * 8 + (lid & 7);   // A row base
    const int kA  = lid >> 4;                                      // A k-seg part
    const int swA = (ra >> 1) & 3;
    const int rb  = wn * 32 + ((lid >> 4) & 1) * 8 + (lid & 7);   // B row base
    const int kB  = (lid >> 3) & 1;
    const int swB = (rb >> 1) & 3;

    g1_load(sb, m0, n0, 0, tid);              CP_COMMIT();
    g1_load(sb + G1_STAGE, m0, n0, 32, tid);  CP_COMMIT();

    for (int i = 0; i < 128; i++) {
        if (i + 2 < 128) g1_load(sb + ((i + 2) % 3) * G1_STAGE, m0, n0, (i + 2) * 32, tid);
        CP_COMMIT();
        CP_WAIT(2);
        __syncthreads();
        const uint32_t st = sb + (uint32_t)(i % 3) * G1_STAGE;

#pragma unroll
        for (int ks = 0; ks < 2; ks++) {
            uint32_t ah[2][4], al[2][4], bb[2][4];
#pragma unroll
            for (int mt = 0; mt < 2; mt++) {
                const uint32_t aoff = (uint32_t)((ra + 16 * mt) * 64 +
                                      (((2 * ks + kA) ^ swA) << 4));
                LDSM_X4(ah[mt][0], ah[mt][1], ah[mt][2], ah[mt][3], st + aoff);
                LDSM_X4(al[mt][0], al[mt][1], al[mt][2], al[mt][3], st + 8192 + aoff);
            }
#pragma unroll
            for (int p = 0; p < 2; p++) {
                const uint32_t boff = (uint32_t)((rb + 16 * p) * 64 +
                                      (((2 * ks + kB) ^ swB) << 4));
                LDSM_X4(bb[p][0], bb[p][1], bb[p][2], bb[p][3], st + 16384 + boff);
            }
#pragma unroll
            for (int mt = 0; mt < 2; mt++)
#pragma unroll
                for (int nt = 0; nt < 4; nt++) {
                    mma16816(accM[mt][nt], ah[mt], &bb[nt >> 1][(nt & 1) * 2]);
                    mma16816(accC[mt][nt], al[mt], &bb[nt >> 1][(nt & 1) * 2]);
                }
#pragma unroll
            for (int p = 0; p < 2; p++) {      // reload B regs with lo plane
                const uint32_t boff = (uint32_t)((rb + 16 * p) * 64 +
                                      (((2 * ks + kB) ^ swB) << 4));
                LDSM_X4(bb[p][0], bb[p][1], bb[p][2], bb[p][3], st + 24576 + boff);
            }
#pragma unroll
            for (int mt = 0; mt < 2; mt++)
#pragma unroll
                for (int nt = 0; nt < 4; nt++)
                    mma16816(accC[mt][nt], ah[mt], &bb[nt >> 1][(nt & 1) * 2]);
        }
        __syncthreads();
    }

    // epilogue: combine, bias, relu, split to (hi, lo*2048) halves
    const int er = lid >> 2, ec = 2 * (lid & 3);
#pragma unroll
    for (int mt = 0; mt < 2; mt++) {
        const int m = m0 + wm * 32 + mt * 16 + er;
#pragma unroll
        for (int nt = 0; nt < 4; nt++) {
            const int n = n0 + wn * 32 + nt * 8 + ec;
            const float bb0 = __ldg(b1 + n), bb1 = __ldg(b1 + n + 1);
#pragma unroll
            for (int half_m = 0; half_m < 2; half_m++) {
                const int mm = m + 8 * half_m;
                const float v0 = fmaxf(accM[mt][nt][2 * half_m + 0] +
                                       accC[mt][nt][2 * half_m + 0] * LO_INV + bb0, 0.0f);
                const float v1 = fmaxf(accM[mt][nt][2 * half_m + 1] +
                                       accC[mt][nt][2 * half_m + 1] * LO_INV + bb1, 0.0f);
                const __half h0 = __float2half_rn(v0), h1 = __float2half_rn(v1);
                const __half l0 = __float2half_rn((v0 - __half2float(h0)) * LO_SCALE);
                const __half l1 = __float2half_rn((v1 - __half2float(h1)) * LO_SCALE);
                *(__half2*)(g_hh + (size_t)mm * H_DIM + n) = __halves2half2(h0, h1);
                *(__half2*)(g_hl + (size_t)mm * H_DIM + n) = __halves2half2(l0, l1);
            }
        }
    }
}

// ============================================================================
// GEMM2: logits = h @ W2^T + b2 (M=16384, N=64, K=2048) + fused routing.
// 256 threads = 8 warps (4m x 2n), warp tile 32x32. Stage: A 16K | B 8K; x3 = 72KB.
// ============================================================================
#define G2_STAGE 24576
#define G2_SMEM  (3 * G2_STAGE)

__device__ __forceinline__ void g2_load(uint32_t stg, int m0, int k0, int tid) {
    const __half* aplane[2] = { g_hh,  g_hl };
    const __half* bplane[2] = { g_w2h, g_w2l };
#pragma unroll
    for (int t = 0; t < 4; t++) {              // A: 1024 cp
        const int q = tid + t * 256;
        const int pl = q >> 9, r = (q >> 2) & 127, seg = q & 3;
        CP_ASYNC16(stg + pl * 8192 + plane_off(r, seg),
                   aplane[pl] + (size_t)(m0 + r) * H_DIM + k0 + seg * 8);
    }
#pragma unroll
    for (int t = 0; t < 2; t++) {              // B: 512 cp (64 rows x 4 segs x 2 planes)
        const int q = tid + t * 256;
        const int pl = q >> 8, r = (q >> 2) & 63, seg = q & 3;
        CP_ASYNC16(stg + 16384 + pl * 4096 + plane_off(r, seg),
                   bplane[pl] + (size_t)r * H_DIM + k0 + seg * 8);
    }
}

__global__ void __launch_bounds__(256)
g2_kernel(const float* __restrict__ b2, float* __restrict__ out) {
    extern __shared__ __align__(1024) char smem[];
    const int tid = threadIdx.x;
    const int wid = tid >> 5, lid = tid & 31;
    const int wm = wid >> 1, wn = wid & 1;        // 4m x 2n grid, 32x32 tiles
    const int m0 = (int)blockIdx.x * 128;
    const uint32_t sb = smem_u32(smem);

    float accM[2][4][4], accC[2][4][4];
#pragma unroll
    for (int a = 0; a < 2; a++)
#pragma unroll
        for (int b = 0; b < 4; b++)
#pragma unroll
            for (int c = 0; c < 4; c++) { accM[a][b][c] = 0.0f; accC[a][b][c] = 0.0f; }

    const int ra  = wm * 32 + ((lid >> 3) & 1) * 8 + (lid & 7);
    const int kA  = lid >> 4;
    const int swA = (ra >> 1) & 3;
    const int rb  = wn * 32 + ((lid >> 4) & 1) * 8 + (lid & 7);
    const int kB  = (lid >> 3) & 1;
    const int swB = (rb >> 1) & 3;

    g2_load(sb, m0, 0, tid);              CP_COMMIT();
    g2_load(sb + G2_STAGE, m0, 32, tid);  CP_COMMIT();

    for (int i = 0; i < 64; i++) {
        if (i + 2 < 64) g2_load(sb + ((i + 2) % 3) * G2_STAGE, m0, (i + 2) * 32, tid);
        CP_COMMIT();
        CP_WAIT(2);
        __syncthreads();
        const uint32_t st = sb + (uint32_t)(i % 3) * G2_STAGE;

#pragma unroll
        for (int ks = 0; ks < 2; ks++) {
            uint32_t ah[2][4], al[2][4], bb[2][4];
#pragma unroll
            for (int mt = 0; mt < 2; mt++) {
                const uint32_t aoff = (uint32_t)((ra + 16 * mt) * 64 +
                                      (((2 * ks + kA) ^ swA) << 4));
                LDSM_X4(ah[mt][0], ah[mt][1], ah[mt][2], ah[mt][3], st + aoff);
                LDSM_X4(al[mt][0], al[mt][1], al[mt][2], al[mt][3], st + 8192 + aoff);
            }
#pragma unroll
            for (int p = 0; p < 2; p++) {
                const uint32_t boff = (uint32_t)((rb + 16 * p) * 64 +
                                      (((2 * ks + kB) ^ swB) << 4));
                LDSM_X4(bb[p][0], bb[p][1], bb[p][2], bb[p][3], st + 16384 + boff);
            }
#pragma unroll
            for (int mt = 0; mt < 2; mt++)
#pragma unroll
                for (int nt = 0; nt < 4; nt++) {
                    mma16816(accM[mt][nt], ah[mt], &bb[nt >> 1][(nt & 1) * 2]);
                    mma16816(accC[mt][nt], al[mt], &bb[nt >> 1][(nt & 1) * 2]);
                }
#pragma unroll
            for (int p = 0; p < 2; p++) {
                const uint32_t boff = (uint32_t)((rb + 16 * p) * 64 +
                                      (((2 * ks + kB) ^ swB) << 4));
                LDSM_X4(bb[p][0], bb[p][1], bb[p][2], bb[p][3], st + 16384 + 4096 + boff);
            }
#pragma unroll
            for (int mt = 0; mt < 2; mt++)
#pragma unroll
                for (int nt = 0; nt < 4; nt++)
                    mma16816(accC[mt][nt], ah[mt], &bb[nt >> 1][(nt & 1) * 2]);
        }
        __syncthreads();
    }

    // ---- logits (+bias) to smem, stride 65 ----
    float* lg = (float*)smem;                   // 128 x 65 floats = 33.3 KB < 72 KB
    const int er = lid >> 2, ec = 2 * (lid & 3);
#pragma unroll
    for (int mt = 0; mt < 2; mt++) {
        const int rr = wm * 32 + mt * 16 + er;
#pragma unroll
        for (int nt = 0; nt < 4; nt++) {
            const int cc = wn * 32 + nt * 8 + ec;
            const float bb0 = __ldg(b2 + cc), bb1 = __ldg(b2 + cc + 1);
            lg[rr * 65 + cc]           = accM[mt][nt][0] + accC[mt][nt][0] * LO_INV + bb0;
            lg[rr * 65 + cc + 1]       = accM[mt][nt][1] + accC[mt][nt][1] * LO_INV + bb1;
            lg[(rr + 8) * 65 + cc]     = accM[mt][nt][2] + accC[mt][nt][2] * LO_INV + bb0;
            lg[(rr + 8) * 65 + cc + 1] = accM[mt][nt][3] + accC[mt][nt][3] * LO_INV + bb1;
        }
    }
    __syncthreads();

    // ---- per-row routing: threads 0..127 own one row each ----
    float e_red = 0.0f;
    if (tid < 128) {
        float l[64];
#pragma unroll
        for (int j = 0; j < 64; j++) l[j] = lg[tid * 65 + j];

        float b1v = l[0], b2v = -3.4e38f;
        int i1 = 0, i2 = 0;
#pragma unroll
        for (int j = 1; j < 64; j++) {
            const float v = l[j];
            if (v > b1v)      { b2v = b1v; i2 = i1; b1v = v; i1 = j; }
            else if (v > b2v) { b2v = v; i2 = j; }
        }
        const float e2 = __expf((b2v - b1v) / TEMP);
        const float w0 = 1.0f / (1.0f + e2);
        const float w1v = e2 / (1.0f + e2);

        float S = 0.0f;
#pragma unroll
        for (int j = 0; j < 64; j++) S += expf(l[j] - b1v);
        const float invS = 1.0f / S;
        float ent = 0.0f;
#pragma unroll
        for (int j = 0; j < 64; j++) {
            const float p = expf(l[j] - b1v) * invS;
            ent -= p * logf(p + 1e-10f);
        }

        const int r = m0 + tid;
        out[2 * r + 0] = w0;
        out[2 * r + 1] = w1v;
        out[2 * B_ROWS + 2 * r + 0] = (float)i1;
        out[2 * B_ROWS + 2 * r + 1] = (float)i2;

        float e = ent;
#pragma unroll
        for (int o = 16; o > 0; o >>= 1) e += __shfl_down_sync(0xffffffffu, e, o);
        e_red = e;
    }
    __syncthreads();
    float* part = lg + 128 * 65;
    if (tid < 128 && (tid & 31) == 0) part[tid >> 5] = e_red;
    __syncthreads();
    if (tid == 0) g_part[blockIdx.x] = part[0] + part[1] + part[2] + part[3];
}

// ---------------- finalize: deterministic mean entropy ----------------
__global__ void fin_kernel(float* __restrict__ out) {
    if (threadIdx.x == 0) {
        float s = 0.0f;
        for (int i = 0; i < B_ROWS / 128; i++) s += g_part[i];
        out[2 * B_ROWS * 2] = (s / (float)B_ROWS) / logf((float)E_DIM);
    }
}

// ---------------- launch ----------------
extern "C" void kernel_launch(void* const* d_in, const int* in_sizes, int n_in,
                              void* d_out, int out_size) {
    const float* x  = (const float*)d_in[0];
    const float* W1 = (const float*)d_in[1];
    const float* b1 = (const float*)d_in[2];
    const float* W2 = (const float*)d_in[3];
    const float* b2 = (const float*)d_in[4];
    float* out = (float*)d_out;
    (void)in_sizes; (void)n_in; (void)out_size;

    cudaFuncSetAttribute(g1_kernel, cudaFuncAttributeMaxDynamicSharedMemorySize, G1_SMEM);
    cudaFuncSetAttribute(g2_kernel, cudaFuncAttributeMaxDynamicSharedMemorySize, G2_SMEM);

    __half *xh, *xl, *w1h, *w1l, *w2h, *w2l;
    cudaGetSymbolAddress((void**)&xh,  g_xh);
    cudaGetSymbolAddress((void**)&xl,  g_xl);
    cudaGetSymbolAddress((void**)&w1h, g_w1h);
    cudaGetSymbolAddress((void**)&w1l, g_w1l);
    cudaGetSymbolAddress((void**)&w2h, g_w2h);
    cudaGetSymbolAddress((void**)&w2l, g_w2l);

    split_kernel<<<4096, 256>>>(x,  xh,  xl,  (B_ROWS * D_DIM) / 4);
    split_kernel<<<2048, 256>>>(W1, w1h, w1l, (H_DIM * D_DIM) / 4);
    split_kernel<<<64,   256>>>(W2, w2h, w2l, (E_DIM * H_DIM) / 4);

    g1_kernel<<<(B_ROWS / 128) * (H_DIM / 128), 512, G1_SMEM>>>(b1);  // 2048 CTAs
    g2_kernel<<<B_ROWS / 128, 256, G2_SMEM>>>(b2, out);               // 128 CTAs
    fin_kernel<<<1, 32>>>(out);
}

// round 9
// speedup vs baseline: 2.1759x; 1.3613x over previous
#include <cuda_runtime.h>
#include <cuda_fp16.h>
#include <cstdint>
#include <cstddef>

// ---------------- problem dims ----------------
#define B_ROWS 16384
#define D_DIM  4096
#define H_DIM  2048
#define E_DIM  64
#define TEMP   0.8f
#define LO_SCALE 2048.0f
#define LO_INV   4.8828125e-4f   // 1/2048

// out (float32): [0,32768) weights, [32768,65536) indices (as float), [65536] uncertainty

// ---------------- device scratch (split half planes) ----------------
__device__ __half g_xh[(size_t)B_ROWS * D_DIM];
__device__ __half g_xl[(size_t)B_ROWS * D_DIM];
__device__ __half g_w1h[(size_t)H_DIM * D_DIM];
__device__ __half g_w1l[(size_t)H_DIM * D_DIM];
__device__ __half g_w2h[(size_t)E_DIM * H_DIM];
__device__ __half g_w2l[(size_t)E_DIM * H_DIM];
__device__ __half g_hh[(size_t)B_ROWS * H_DIM];
__device__ __half g_hl[(size_t)B_ROWS * H_DIM];
__device__ float  g_part[B_ROWS / 128];

// ---------------- helpers ----------------
__device__ __forceinline__ uint32_t smem_u32(const void* p) {
    uint32_t a;
    asm("{ .reg .u64 t; cvta.to.shared.u64 t, %1; cvt.u32.u64 %0, t; }" : "=r"(a) : "l"(p));
    return a;
}

#define CP_ASYNC16(saddr, gptr) \
    asm volatile("cp.async.cg.shared.global [%0], [%1], 16;" :: "r"(saddr), "l"(gptr) : "memory")
#define CP_COMMIT() asm volatile("cp.async.commit_group;" ::: "memory")
#define CP_WAIT(n)  asm volatile("cp.async.wait_group %0;" :: "n"(n) : "memory")

#define LDSM_X4(r0, r1, r2, r3, addr) \
    asm volatile("ldmatrix.sync.aligned.m8n8.x4.shared.b16 {%0,%1,%2,%3}, [%4];" \
                 : "=r"(r0), "=r"(r1), "=r"(r2), "=r"(r3) : "r"(addr))

__device__ __forceinline__ void mma16816(float* d, const uint32_t* a, const uint32_t* b) {
    asm volatile(
        "mma.sync.aligned.m16n8k16.row.col.f32.f16.f16.f32 "
        "{%0,%1,%2,%3}, {%4,%5,%6,%7}, {%8,%9}, {%0,%1,%2,%3};"
        : "+f"(d[0]), "+f"(d[1]), "+f"(d[2]), "+f"(d[3])
        : "r"(a[0]), "r"(a[1]), "r"(a[2]), "r"(a[3]), "r"(b[0]), "r"(b[1]));
}

// plane row = 32 halfs = 64B; 16B segs swizzled: seg' = seg ^ ((row>>1)&3)
__device__ __forceinline__ uint32_t plane_off(int row, int seg) {
    return (uint32_t)(row * 64 + ((seg ^ ((row >> 1) & 3)) << 4));
}

// ---------------- prepass: split fp32 -> (hi, lo*2048) fp16 planes ----------------
__global__ void split_kernel(const float* __restrict__ src, __half* __restrict__ hi,
                             __half* __restrict__ lo, int n4) {
    for (int i = blockIdx.x * blockDim.x + threadIdx.x; i < n4; i += gridDim.x * blockDim.x) {
        float4 v = ((const float4*)src)[i];
        __half h0 = __float2half_rn(v.x), h1 = __float2half_rn(v.y);
        __half h2 = __float2half_rn(v.z), h3 = __float2half_rn(v.w);
        __half l0 = __float2half_rn((v.x - __half2float(h0)) * LO_SCALE);
        __half l1 = __float2half_rn((v.y - __half2float(h1)) * LO_SCALE);
        __half l2 = __float2half_rn((v.z - __half2float(h2)) * LO_SCALE);
        __half l3 = __float2half_rn((v.w - __half2float(h3)) * LO_SCALE);
        ((__half2*)hi)[2 * i]     = __halves2half2(h0, h1);
        ((__half2*)hi)[2 * i + 1] = __halves2half2(h2, h3);
        ((__half2*)lo)[2 * i]     = __halves2half2(l0, l1);
        ((__half2*)lo)[2 * i + 1] = __halves2half2(l2, l3);
    }
}

// ============================================================================
// GEMM1: h = relu(x @ W1^T + b1). 128x64 CTA tile, 256 thr (8 warps, 4m x 2n of
// 32x32), 2 CTAs/SM, K-chunk 32, 3-stage cp.async, ONE sync per chunk.
// Stage: A_hi 8K | A_lo 8K | B_hi 4K | B_lo 4K = 24KB; 3 stages = 72KB.
// ============================================================================
#define G1_STAGE 24576
#define G1_SMEM  (3 * G1_STAGE)

__device__ __forceinline__ void g1_load(uint32_t stg, int m0, int n0, int k0, int tid) {
#pragma unroll
    for (int t = 0; t < 4; t++) {              // A: 1024 cp (128 rows x 4 segs x 2 planes)
        const int q = tid + t * 256;
        const int pl = q >> 9, r = (q >> 2) & 127, seg = q & 3;
        const __half* ap = pl ? g_xl : g_xh;
        CP_ASYNC16(stg + pl * 8192 + plane_off(r, seg),
                   ap + (size_t)(m0 + r) * D_DIM + k0 + seg * 8);
    }
#pragma unroll
    for (int t = 0; t < 2; t++) {              // B: 512 cp (64 rows x 4 segs x 2 planes)
        const int q = tid + t * 256;
        const int pl = q >> 8, r = (q >> 2) & 63, seg = q & 3;
        const __half* bp = pl ? g_w1l : g_w1h;
        CP_ASYNC16(stg + 16384 + pl * 4096 + plane_off(r, seg),
                   bp + (size_t)(n0 + r) * D_DIM + k0 + seg * 8);
    }
}

__global__ void __launch_bounds__(256, 2)
g1_kernel(const float* __restrict__ b1) {
    extern __shared__ __align__(1024) char smem[];
    const int tid = threadIdx.x;
    const int wid = tid >> 5, lid = tid & 31;
    const int wm = wid >> 1, wn = wid & 1;          // 4m x 2n grid, 32x32 tiles
    const int m0 = (int)(blockIdx.x >> 5) * 128;    // n-fastest: W1 L2-resident
    const int n0 = (int)(blockIdx.x & 31) * 64;
    const uint32_t sb = smem_u32(smem);

    float accM[2][4][4], accC[2][4][4];
#pragma unroll
    for (int a = 0; a < 2; a++)
#pragma unroll
        for (int b = 0; b < 4; b++)
#pragma unroll
            for (int c = 0; c < 4; c++) { accM[a][b][c] = 0.0f; accC[a][b][c] = 0.0f; }

    const int ra  = wm * 32 + ((lid >> 3) & 1) * 8 + (lid & 7);
    const int kA  = lid >> 4;
    const int swA = (ra >> 1) & 3;
    const int rb  = wn * 32 + ((lid >> 4) & 1) * 8 + (lid & 7);
    const int kB  = (lid >> 3) & 1;
    const int swB = (rb >> 1) & 3;

    g1_load(sb, m0, n0, 0, tid);              CP_COMMIT();
    g1_load(sb + G1_STAGE, m0, n0, 32, tid);  CP_COMMIT();

    for (int i = 0; i < 128; i++) {
        CP_WAIT(1);
        __syncthreads();
        const uint32_t st = sb + (uint32_t)(i % 3) * G1_STAGE;

#pragma unroll
        for (int ks = 0; ks < 2; ks++) {
            uint32_t ah[2][4], al[2][4], bb[2][4];
#pragma unroll
            for (int mt = 0; mt < 2; mt++) {
                const uint32_t aoff = (uint32_t)((ra + 16 * mt) * 64 +
                                      (((2 * ks + kA) ^ swA) << 4));
                LDSM_X4(ah[mt][0], ah[mt][1], ah[mt][2], ah[mt][3], st + aoff);
                LDSM_X4(al[mt][0], al[mt][1], al[mt][2], al[mt][3], st + 8192 + aoff);
            }
#pragma unroll
            for (int p = 0; p < 2; p++) {
                const uint32_t boff = (uint32_t)((rb + 16 * p) * 64 +
                                      (((2 * ks + kB) ^ swB) << 4));
                LDSM_X4(bb[p][0], bb[p][1], bb[p][2], bb[p][3], st + 16384 + boff);
            }
#pragma unroll
            for (int mt = 0; mt < 2; mt++)
#pragma unroll
                for (int nt = 0; nt < 4; nt++) {
                    mma16816(accM[mt][nt], ah[mt], &bb[nt >> 1][(nt & 1) * 2]);
                    mma16816(accC[mt][nt], al[mt], &bb[nt >> 1][(nt & 1) * 2]);
                }
#pragma unroll
            for (int p = 0; p < 2; p++) {      // reload B regs with lo plane
                const uint32_t boff = (uint32_t)((rb + 16 * p) * 64 +
                                      (((2 * ks + kB) ^ swB) << 4));
                LDSM_X4(bb[p][0], bb[p][1], bb[p][2], bb[p][3], st + 16384 + 4096 + boff);
            }
#pragma unroll
            for (int mt = 0; mt < 2; mt++)
#pragma unroll
                for (int nt = 0; nt < 4; nt++)
                    mma16816(accC[mt][nt], ah[mt], &bb[nt >> 1][(nt & 1) * 2]);
        }
        // issue next load AFTER compute: writes stage (i-1)%3, which the barrier
        // above proved all warps are done reading.
        if (i + 2 < 128) g1_load(sb + ((i + 2) % 3) * G1_STAGE, m0, n0, (i + 2) * 32, tid);
        CP_COMMIT();
    }

    // epilogue: combine, bias, relu, split to (hi, lo*2048) halves
    const int er = lid >> 2, ec = 2 * (lid & 3);
#pragma unroll
    for (int mt = 0; mt < 2; mt++) {
        const int m = m0 + wm * 32 + mt * 16 + er;
#pragma unroll
        for (int nt = 0; nt < 4; nt++) {
            const int n = n0 + wn * 32 + nt * 8 + ec;
            const float bb0 = __ldg(b1 + n), bb1 = __ldg(b1 + n + 1);
#pragma unroll
            for (int hm = 0; hm < 2; hm++) {
                const int mm = m + 8 * hm;
                const float v0 = fmaxf(accM[mt][nt][2 * hm + 0] +
                                       accC[mt][nt][2 * hm + 0] * LO_INV + bb0, 0.0f);
                const float v1 = fmaxf(accM[mt][nt][2 * hm + 1] +
                                       accC[mt][nt][2 * hm + 1] * LO_INV + bb1, 0.0f);
                const __half h0 = __float2half_rn(v0), h1 = __float2half_rn(v1);
                const __half l0 = __float2half_rn((v0 - __half2float(h0)) * LO_SCALE);
                const __half l1 = __float2half_rn((v1 - __half2float(h1)) * LO_SCALE);
                *(__half2*)(g_hh + (size_t)mm * H_DIM + n) = __halves2half2(h0, h1);
                *(__half2*)(g_hl + (size_t)mm * H_DIM + n) = __halves2half2(l0, l1);
            }
        }
    }
}

// ============================================================================
// GEMM2: logits = h @ W2^T + b2 (M=16384, N=64, K=2048) + fused routing.
// 256 threads = 8 warps (4m x 2n), warp tile 32x32. Stage: A 16K | B 8K; x3 = 72KB.
// ============================================================================
#define G2_STAGE 24576
#define G2_SMEM  (3 * G2_STAGE)

__device__ __forceinline__ void g2_load(uint32_t stg, int m0, int k0, int tid) {
#pragma unroll
    for (int t = 0; t < 4; t++) {              // A: 1024 cp
        const int q = tid + t * 256;
        const int pl = q >> 9, r = (q >> 2) & 127, seg = q & 3;
        const __half* ap = pl ? g_hl : g_hh;
        CP_ASYNC16(stg + pl * 8192 + plane_off(r, seg),
                   ap + (size_t)(m0 + r) * H_DIM + k0 + seg * 8);
    }
#pragma unroll
    for (int t = 0; t < 2; t++) {              // B: 512 cp (64 rows x 4 segs x 2 planes)
        const int q = tid + t * 256;
        const int pl = q >> 8, r = (q >> 2) & 63, seg = q & 3;
        const __half* bp = pl ? g_w2l : g_w2h;
        CP_ASYNC16(stg + 16384 + pl * 4096 + plane_off(r, seg),
                   bp + (size_t)r * H_DIM + k0 + seg * 8);
    }
}

__global__ void __launch_bounds__(256, 2)
g2_kernel(const float* __restrict__ b2, float* __restrict__ out) {
    extern __shared__ __align__(1024) char smem[];
    const int tid = threadIdx.x;
    const int wid = tid >> 5, lid = tid & 31;
    const int wm = wid >> 1, wn = wid & 1;
    const int m0 = (int)blockIdx.x * 128;
    const uint32_t sb = smem_u32(smem);

    float accM[2][4][4], accC[2][4][4];
#pragma unroll
    for (int a = 0; a < 2; a++)
#pragma unroll
        for (int b = 0; b < 4; b++)
#pragma unroll
            for (int c = 0; c < 4; c++) { accM[a][b][c] = 0.0f; accC[a][b][c] = 0.0f; }

    const int ra  = wm * 32 + ((lid >> 3) & 1) * 8 + (lid & 7);
    const int kA  = lid >> 4;
    const int swA = (ra >> 1) & 3;
    const int rb  = wn * 32 + ((lid >> 4) & 1) * 8 + (lid & 7);
    const int kB  = (lid >> 3) & 1;
    const int swB = (rb >> 1) & 3;

    g2_load(sb, m0, 0, tid);              CP_COMMIT();
    g2_load(sb + G2_STAGE, m0, 32, tid);  CP_COMMIT();

    for (int i = 0; i < 64; i++) {
        CP_WAIT(1);
        __syncthreads();
        const uint32_t st = sb + (uint32_t)(i % 3) * G2_STAGE;

#pragma unroll
        for (int ks = 0; ks < 2; ks++) {
            uint32_t ah[2][4], al[2][4], bb[2][4];
#pragma unroll
            for (int mt = 0; mt < 2; mt++) {
                const uint32_t aoff = (uint32_t)((ra + 16 * mt) * 64 +
                                      (((2 * ks + kA) ^ swA) << 4));
                LDSM_X4(ah[mt][0], ah[mt][1], ah[mt][2], ah[mt][3], st + aoff);
                LDSM_X4(al[mt][0], al[mt][1], al[mt][2], al[mt][3], st + 8192 + aoff);
            }
#pragma unroll
            for (int p = 0; p < 2; p++) {
                const uint32_t boff = (uint32_t)((rb + 16 * p) * 64 +
                                      (((2 * ks + kB) ^ swB) << 4));
                LDSM_X4(bb[p][0], bb[p][1], bb[p][2], bb[p][3], st + 16384 + boff);
            }
#pragma unroll
            for (int mt = 0; mt < 2; mt++)
#pragma unroll
                for (int nt = 0; nt < 4; nt++) {
                    mma16816(accM[mt][nt], ah[mt], &bb[nt >> 1][(nt & 1) * 2]);
                    mma16816(accC[mt][nt], al[mt], &bb[nt >> 1][(nt & 1) * 2]);
                }
#pragma unroll
            for (int p = 0; p < 2; p++) {
                const uint32_t boff = (uint32_t)((rb + 16 * p) * 64 +
                                      (((2 * ks + kB) ^ swB) << 4));
                LDSM_X4(bb[p][0], bb[p][1], bb[p][2], bb[p][3], st + 16384 + 4096 + boff);
            }
#pragma unroll
            for (int mt = 0; mt < 2; mt++)
#pragma unroll
                for (int nt = 0; nt < 4; nt++)
                    mma16816(accC[mt][nt], ah[mt], &bb[nt >> 1][(nt & 1) * 2]);
        }
        if (i + 2 < 64) g2_load(sb + ((i + 2) % 3) * G2_STAGE, m0, (i + 2) * 32, tid);
        CP_COMMIT();
    }
    __syncthreads();   // protect smem reuse for logits below

    // ---- logits (+bias) to smem, stride 65 ----
    float* lg = (float*)smem;                   // 128 x 65 floats = 33.3 KB < 72 KB
    const int er = lid >> 2, ec = 2 * (lid & 3);
#pragma unroll
    for (int mt = 0; mt < 2; mt++) {
        const int rr = wm * 32 + mt * 16 + er;
#pragma unroll
        for (int nt = 0; nt < 4; nt++) {
            const int cc = wn * 32 + nt * 8 + ec;
            const float bb0 = __ldg(b2 + cc), bb1 = __ldg(b2 + cc + 1);
            lg[rr * 65 + cc]           = accM[mt][nt][0] + accC[mt][nt][0] * LO_INV + bb0;
            lg[rr * 65 + cc + 1]       = accM[mt][nt][1] + accC[mt][nt][1] * LO_INV + bb1;
            lg[(rr + 8) * 65 + cc]     = accM[mt][nt][2] + accC[mt][nt][2] * LO_INV + bb0;
            lg[(rr + 8) * 65 + cc + 1] = accM[mt][nt][3] + accC[mt][nt][3] * LO_INV + bb1;
        }
    }
    __syncthreads();

    // ---- per-row routing: threads 0..127 own one row each ----
    float e_red = 0.0f;
    if (tid < 128) {
        float l[64];
#pragma unroll
        for (int j = 0; j < 64; j++) l[j] = lg[tid * 65 + j];

        float b1v = l[0], b2v = -3.4e38f;
        int i1 = 0, i2 = 0;
#pragma unroll
        for (int j = 1; j < 64; j++) {
            const float v = l[j];
            if (v > b1v)      { b2v = b1v; i2 = i1; b1v = v; i1 = j; }
            else if (v > b2v) { b2v = v; i2 = j; }
        }
        const float e2 = __expf((b2v - b1v) / TEMP);
        const float w0 = 1.0f / (1.0f + e2);
        const float w1v = e2 / (1.0f + e2);

        float S = 0.0f;
#pragma unroll
        for (int j = 0; j < 64; j++) S += expf(l[j] - b1v);
        const float invS = 1.0f / S;
        float ent = 0.0f;
#pragma unroll
        for (int j = 0; j < 64; j++) {
            const float p = expf(l[j] - b1v) * invS;
            ent -= p * logf(p + 1e-10f);
        }

        const int r = m0 + tid;
        out[2 * r + 0] = w0;
        out[2 * r + 1] = w1v;
        out[2 * B_ROWS + 2 * r + 0] = (float)i1;
        out[2 * B_ROWS + 2 * r + 1] = (float)i2;

        float e = ent;
#pragma unroll
        for (int o = 16; o > 0; o >>= 1) e += __shfl_down_sync(0xffffffffu, e, o);
        e_red = e;
    }
    __syncthreads();
    float* part = lg + 128 * 65;
    if (tid < 128 && (tid & 31) == 0) part[tid >> 5] = e_red;
    __syncthreads();
    if (tid == 0) g_part[blockIdx.x] = part[0] + part[1] + part[2] + part[3];
}

// ---------------- finalize: deterministic mean entropy ----------------
__global__ void fin_kernel(float* __restrict__ out) {
    if (threadIdx.x == 0) {
        float s = 0.0f;
        for (int i = 0; i < B_ROWS / 128; i++) s += g_part[i];
        out[2 * B_ROWS * 2] = (s / (float)B_ROWS) / logf((float)E_DIM);
    }
}

// ---------------- launch ----------------
extern "C" void kernel_launch(void* const* d_in, const int* in_sizes, int n_in,
                              void* d_out, int out_size) {
    const float* x  = (const float*)d_in[0];
    const float* W1 = (const float*)d_in[1];
    const float* b1 = (const float*)d_in[2];
    const float* W2 = (const float*)d_in[3];
    const float* b2 = (const float*)d_in[4];
    float* out = (float*)d_out;
    (void)in_sizes; (void)n_in; (void)out_size;

    cudaFuncSetAttribute(g1_kernel, cudaFuncAttributeMaxDynamicSharedMemorySize, G1_SMEM);
    cudaFuncSetAttribute(g2_kernel, cudaFuncAttributeMaxDynamicSharedMemorySize, G2_SMEM);

    __half *xh, *xl, *w1h, *w1l, *w2h, *w2l;
    cudaGetSymbolAddress((void**)&xh,  g_xh);
    cudaGetSymbolAddress((void**)&xl,  g_xl);
    cudaGetSymbolAddress((void**)&w1h, g_w1h);
    cudaGetSymbolAddress((void**)&w1l, g_w1l);
    cudaGetSymbolAddress((void**)&w2h, g_w2h);
    cudaGetSymbolAddress((void**)&w2l, g_w2l);

    split_kernel<<<4096, 256>>>(x,  xh,  xl,  (B_ROWS * D_DIM) / 4);
    split_kernel<<<2048, 256>>>(W1, w1h, w1l, (H_DIM * D_DIM) / 4);
    split_kernel<<<64,   256>>>(W2, w2h, w2l, (E_DIM * H_DIM) / 4);

    g1_kernel<<<(B_ROWS / 128) * (H_DIM / 64), 256, G1_SMEM>>>(b1);  // 4096 CTAs
    g2_kernel<<<B_ROWS / 128, 256, G2_SMEM>>>(b2, out);              // 128 CTAs
    fin_kernel<<<1, 32>>>(out);
}

// round 10
// speedup vs baseline: 2.3216x; 1.0670x over previous
#include <cuda_runtime.h>
#include <cuda_fp16.h>
#include <cstdint>
#include <cstddef>

// ---------------- problem dims ----------------
#define B_ROWS 16384
#define D_DIM  4096
#define H_DIM  2048
#define E_DIM  64
#define TEMP   0.8f
#define LO_SCALE 2048.0f
#define LO_INV   4.8828125e-4f   // 1/2048

// out (float32): [0,32768) weights, [32768,65536) indices (as float), [65536] uncertainty

// ---------------- device scratch (split half planes) ----------------
__device__ __half g_xh[(size_t)B_ROWS * D_DIM];
__device__ __half g_xl[(size_t)B_ROWS * D_DIM];
__device__ __half g_w1h[(size_t)H_DIM * D_DIM];
__device__ __half g_w1l[(size_t)H_DIM * D_DIM];
__device__ __half g_w2h[(size_t)E_DIM * H_DIM];
__device__ __half g_w2l[(size_t)E_DIM * H_DIM];
__device__ __half g_hh[(size_t)B_ROWS * H_DIM];
__device__ __half g_hl[(size_t)B_ROWS * H_DIM];
__device__ float  g_part[B_ROWS / 128];

// ---------------- helpers ----------------
__device__ __forceinline__ uint32_t smem_u32(const void* p) {
    uint32_t a;
    asm("{ .reg .u64 t; cvta.to.shared.u64 t, %1; cvt.u32.u64 %0, t; }" : "=r"(a) : "l"(p));
    return a;
}

#define CP_ASYNC16(saddr, gptr) \
    asm volatile("cp.async.cg.shared.global [%0], [%1], 16;" :: "r"(saddr), "l"(gptr) : "memory")
#define CP_COMMIT() asm volatile("cp.async.commit_group;" ::: "memory")
#define CP_WAIT(n)  asm volatile("cp.async.wait_group %0;" :: "n"(n) : "memory")

#define LDSM_X4(r0, r1, r2, r3, addr) \
    asm volatile("ldmatrix.sync.aligned.m8n8.x4.shared.b16 {%0,%1,%2,%3}, [%4];" \
                 : "=r"(r0), "=r"(r1), "=r"(r2), "=r"(r3) : "r"(addr))

__device__ __forceinline__ void mma16816(float* d, const uint32_t* a, const uint32_t* b) {
    asm volatile(
        "mma.sync.aligned.m16n8k16.row.col.f32.f16.f16.f32 "
        "{%0,%1,%2,%3}, {%4,%5,%6,%7}, {%8,%9}, {%0,%1,%2,%3};"
        : "+f"(d[0]), "+f"(d[1]), "+f"(d[2]), "+f"(d[3])
        : "r"(a[0]), "r"(a[1]), "r"(a[2]), "r"(a[3]), "r"(b[0]), "r"(b[1]));
}

// plane row = 64 halfs = 128B; 8 segs of 16B, swizzled: seg' = seg ^ (row & 7)
__device__ __forceinline__ uint32_t plane_off(int row, int seg) {
    return (uint32_t)(row * 128 + ((seg ^ (row & 7)) << 4));
}

// ---------------- prepass: split fp32 -> (hi, lo*2048) fp16 planes ----------------
__global__ void split_kernel(const float* __restrict__ src, __half* __restrict__ hi,
                             __half* __restrict__ lo, int n4) {
    for (int i = blockIdx.x * blockDim.x + threadIdx.x; i < n4; i += gridDim.x * blockDim.x) {
        float4 v = ((const float4*)src)[i];
        __half h0 = __float2half_rn(v.x), h1 = __float2half_rn(v.y);
        __half h2 = __float2half_rn(v.z), h3 = __float2half_rn(v.w);
        __half l0 = __float2half_rn((v.x - __half2float(h0)) * LO_SCALE);
        __half l1 = __float2half_rn((v.y - __half2float(h1)) * LO_SCALE);
        __half l2 = __float2half_rn((v.z - __half2float(h2)) * LO_SCALE);
        __half l3 = __float2half_rn((v.w - __half2float(h3)) * LO_SCALE);
        ((__half2*)hi)[2 * i]     = __halves2half2(h0, h1);
        ((__half2*)hi)[2 * i + 1] = __halves2half2(h2, h3);
        ((__half2*)lo)[2 * i]     = __halves2half2(l0, l1);
        ((__half2*)lo)[2 * i + 1] = __halves2half2(l2, l3);
    }
}

// ============================================================================
// GEMM1: h = relu(x @ W1^T + b1). 128x64 CTA tile, 256 thr (8 warps, 4m x 2n of
// 32x32), 2 CTAs/SM. K-chunk 64, 2-stage cp.async, load issued BEFORE compute.
// Stage: A_hi 16K | A_lo 16K | B_hi 8K | B_lo 8K = 48KB; 2 stages = 96KB.
// ============================================================================
#define G1_STAGE 49152
#define G1_SMEM  (2 * G1_STAGE)

__device__ __forceinline__ void g1_load(uint32_t stg, int m0, int n0, int k0, int tid) {
#pragma unroll
    for (int t = 0; t < 8; t++) {              // A: 2048 cp (128 rows x 8 segs x 2 planes)
        const int q = tid + t * 256;
        const int pl = q >> 10, r = (q >> 3) & 127, seg = q & 7;
        const __half* ap = pl ? g_xl : g_xh;
        CP_ASYNC16(stg + pl * 16384 + plane_off(r, seg),
                   ap + (size_t)(m0 + r) * D_DIM + k0 + seg * 8);
    }
#pragma unroll
    for (int t = 0; t < 4; t++) {              // B: 1024 cp (64 rows x 8 segs x 2 planes)
        const int q = tid + t * 256;
        const int pl = q >> 9, r = (q >> 3) & 63, seg = q & 7;
        const __half* bp = pl ? g_w1l : g_w1h;
        CP_ASYNC16(stg + 32768 + pl * 8192 + plane_off(r, seg),
                   bp + (size_t)(n0 + r) * D_DIM + k0 + seg * 8);
    }
}

__global__ void __launch_bounds__(256, 2)
g1_kernel(const float* __restrict__ b1) {
    extern __shared__ __align__(1024) char smem[];
    const int tid = threadIdx.x;
    const int wid = tid >> 5, lid = tid & 31;
    const int wm = wid >> 1, wn = wid & 1;          // 4m x 2n grid, 32x32 tiles
    const int m0 = (int)(blockIdx.x >> 5) * 128;    // n-fastest: W1 L2-resident
    const int n0 = (int)(blockIdx.x & 31) * 64;
    const uint32_t sb = smem_u32(smem);

    float accM[2][4][4], accC[2][4][4];
#pragma unroll
    for (int a = 0; a < 2; a++)
#pragma unroll
        for (int b = 0; b < 4; b++)
#pragma unroll
            for (int c = 0; c < 4; c++) { accM[a][b][c] = 0.0f; accC[a][b][c] = 0.0f; }

    // ldmatrix lane geometry (row parts constant; k-seg part per lane)
    const int ra  = wm * 32 + ((lid >> 3) & 1) * 8 + (lid & 7);   // A row
    const int kA  = lid >> 4;                                      // 16B seg within k16
    const int swA = ra & 7;
    const int rb  = wn * 32 + ((lid >> 4) & 1) * 8 + (lid & 7);   // B row
    const int kB  = (lid >> 3) & 1;
    const int swB = rb & 7;

    g1_load(sb, m0, n0, 0, tid);  CP_COMMIT();

    for (int i = 0; i < 64; i++) {
        CP_WAIT(0);
        __syncthreads();
        // issue next chunk's load into the other stage (its readers finished
        // before the barrier above), THEN compute this chunk.
        if (i + 1 < 64) g1_load(sb + ((i + 1) & 1) * G1_STAGE, m0, n0, (i + 1) * 64, tid);
        CP_COMMIT();
        const uint32_t st = sb + (uint32_t)(i & 1) * G1_STAGE;

#pragma unroll
        for (int ks = 0; ks < 4; ks++) {
            uint32_t ah[2][4], al[2][4], bb[2][4];
#pragma unroll
            for (int mt = 0; mt < 2; mt++) {
                const uint32_t aoff = (uint32_t)((ra + 16 * mt) * 128 +
                                      (((2 * ks + kA) ^ swA) << 4));
                LDSM_X4(ah[mt][0], ah[mt][1], ah[mt][2], ah[mt][3], st + aoff);
                LDSM_X4(al[mt][0], al[mt][1], al[mt][2], al[mt][3], st + 16384 + aoff);
            }
#pragma unroll
            for (int p = 0; p < 2; p++) {
                const uint32_t boff = (uint32_t)((rb + 16 * p) * 128 +
                                      (((2 * ks + kB) ^ swB) << 4));
                LDSM_X4(bb[p][0], bb[p][1], bb[p][2], bb[p][3], st + 32768 + boff);
            }
#pragma unroll
            for (int mt = 0; mt < 2; mt++)
#pragma unroll
                for (int nt = 0; nt < 4; nt++) {
                    mma16816(accM[mt][nt], ah[mt], &bb[nt >> 1][(nt & 1) * 2]);
                    mma16816(accC[mt][nt], al[mt], &bb[nt >> 1][(nt & 1) * 2]);
                }
#pragma unroll
            for (int p = 0; p < 2; p++) {      // reload B regs with lo plane
                const uint32_t boff = (uint32_t)((rb + 16 * p) * 128 +
                                      (((2 * ks + kB) ^ swB) << 4));
                LDSM_X4(bb[p][0], bb[p][1], bb[p][2], bb[p][3], st + 32768 + 8192 + boff);
            }
#pragma unroll
            for (int mt = 0; mt < 2; mt++)
#pragma unroll
                for (int nt = 0; nt < 4; nt++)
                    mma16816(accC[mt][nt], ah[mt], &bb[nt >> 1][(nt & 1) * 2]);
        }
    }

    // epilogue: combine, bias, relu, split to (hi, lo*2048) halves
    const int er = lid >> 2, ec = 2 * (lid & 3);
#pragma unroll
    for (int mt = 0; mt < 2; mt++) {
        const int m = m0 + wm * 32 + mt * 16 + er;
#pragma unroll
        for (int nt = 0; nt < 4; nt++) {
            const int n = n0 + wn * 32 + nt * 8 + ec;
            const float bb0 = __ldg(b1 + n), bb1 = __ldg(b1 + n + 1);
#pragma unroll
            for (int hm = 0; hm < 2; hm++) {
                const int mm = m + 8 * hm;
                const float v0 = fmaxf(accM[mt][nt][2 * hm + 0] +
                                       accC[mt][nt][2 * hm + 0] * LO_INV + bb0, 0.0f);
                const float v1 = fmaxf(accM[mt][nt][2 * hm + 1] +
                                       accC[mt][nt][2 * hm + 1] * LO_INV + bb1, 0.0f);
                const __half h0 = __float2half_rn(v0), h1 = __float2half_rn(v1);
                const __half l0 = __float2half_rn((v0 - __half2float(h0)) * LO_SCALE);
                const __half l1 = __float2half_rn((v1 - __half2float(h1)) * LO_SCALE);
                *(__half2*)(g_hh + (size_t)mm * H_DIM + n) = __halves2half2(h0, h1);
                *(__half2*)(g_hl + (size_t)mm * H_DIM + n) = __halves2half2(l0, l1);
            }
        }
    }
}

// ============================================================================
// GEMM2: logits = h @ W2^T + b2 (M=16384, N=64, K=2048) + fused routing.
// Same machinery: K-chunk 64, 2-stage, 256 thr, 32 chunks.
// ============================================================================
#define G2_STAGE 49152
#define G2_SMEM  (2 * G2_STAGE)

__device__ __forceinline__ void g2_load(uint32_t stg, int m0, int k0, int tid) {
#pragma unroll
    for (int t = 0; t < 8; t++) {              // A: 2048 cp
        const int q = tid + t * 256;
        const int pl = q >> 10, r = (q >> 3) & 127, seg = q & 7;
        const __half* ap = pl ? g_hl : g_hh;
        CP_ASYNC16(stg + pl * 16384 + plane_off(r, seg),
                   ap + (size_t)(m0 + r) * H_DIM + k0 + seg * 8);
    }
#pragma unroll
    for (int t = 0; t < 4; t++) {              // B: 1024 cp
        const int q = tid + t * 256;
        const int pl = q >> 9, r = (q >> 3) & 63, seg = q & 7;
        const __half* bp = pl ? g_w2l : g_w2h;
        CP_ASYNC16(stg + 32768 + pl * 8192 + plane_off(r, seg),
                   bp + (size_t)r * H_DIM + k0 + seg * 8);
    }
}

__global__ void __launch_bounds__(256, 2)
g2_kernel(const float* __restrict__ b2, float* __restrict__ out) {
    extern __shared__ __align__(1024) char smem[];
    const int tid = threadIdx.x;
    const int wid = tid >> 5, lid = tid & 31;
    const int wm = wid >> 1, wn = wid & 1;
    const int m0 = (int)blockIdx.x * 128;
    const uint32_t sb = smem_u32(smem);

    float accM[2][4][4], accC[2][4][4];
#pragma unroll
    for (int a = 0; a < 2; a++)
#pragma unroll
        for (int b = 0; b < 4; b++)
#pragma unroll
            for (int c = 0; c < 4; c++) { accM[a][b][c] = 0.0f; accC[a][b][c] = 0.0f; }

    const int ra  = wm * 32 + ((lid >> 3) & 1) * 8 + (lid & 7);
    const int kA  = lid >> 4;
    const int swA = ra & 7;
    const int rb  = wn * 32 + ((lid >> 4) & 1) * 8 + (lid & 7);
    const int kB  = (lid >> 3) & 1;
    const int swB = rb & 7;

    g2_load(sb, m0, 0, tid);  CP_COMMIT();

    for (int i = 0; i < 32; i++) {
        CP_WAIT(0);
        __syncthreads();
        if (i + 1 < 32) g2_load(sb + ((i + 1) & 1) * G2_STAGE, m0, (i + 1) * 64, tid);
        CP_COMMIT();
        const uint32_t st = sb + (uint32_t)(i & 1) * G2_STAGE;

#pragma unroll
        for (int ks = 0; ks < 4; ks++) {
            uint32_t ah[2][4], al[2][4], bb[2][4];
#pragma unroll
            for (int mt = 0; mt < 2; mt++) {
                const uint32_t aoff = (uint32_t)((ra + 16 * mt) * 128 +
                                      (((2 * ks + kA) ^ swA) << 4));
                LDSM_X4(ah[mt][0], ah[mt][1], ah[mt][2], ah[mt][3], st + aoff);
                LDSM_X4(al[mt][0], al[mt][1], al[mt][2], al[mt][3], st + 16384 + aoff);
            }
#pragma unroll
            for (int p = 0; p < 2; p++) {
                const uint32_t boff = (uint32_t)((rb + 16 * p) * 128 +
                                      (((2 * ks + kB) ^ swB) << 4));
                LDSM_X4(bb[p][0], bb[p][1], bb[p][2], bb[p][3], st + 32768 + boff);
            }
#pragma unroll
            for (int mt = 0; mt < 2; mt++)
#pragma unroll
                for (int nt = 0; nt < 4; nt++) {
                    mma16816(accM[mt][nt], ah[mt], &bb[nt >> 1][(nt & 1) * 2]);
                    mma16816(accC[mt][nt], al[mt], &bb[nt >> 1][(nt & 1) * 2]);
                }
#pragma unroll
            for (int p = 0; p < 2; p++) {
                const uint32_t boff = (uint32_t)((rb + 16 * p) * 128 +
                                      (((2 * ks + kB) ^ swB) << 4));
                LDSM_X4(bb[p][0], bb[p][1], bb[p][2], bb[p][3], st + 32768 + 8192 + boff);
            }
#pragma unroll
            for (int mt = 0; mt < 2; mt++)
#pragma unroll
                for (int nt = 0; nt < 4; nt++)
                    mma16816(accC[mt][nt], ah[mt], &bb[nt >> 1][(nt & 1) * 2]);
        }
    }
    __syncthreads();   // protect smem reuse for logits below

    // ---- logits (+bias) to smem, stride 65 ----
    float* lg = (float*)smem;                   // 128 x 65 floats = 33.3 KB < 96 KB
    const int er = lid >> 2, ec = 2 * (lid & 3);
#pragma unroll
    for (int mt = 0; mt < 2; mt++) {
        const int rr = wm * 32 + mt * 16 + er;
#pragma unroll
        for (int nt = 0; nt < 4; nt++) {
            const int cc = wn * 32 + nt * 8 + ec;
            const float bb0 = __ldg(b2 + cc), bb1 = __ldg(b2 + cc + 1);
            lg[rr * 65 + cc]           = accM[mt][nt][0] + accC[mt][nt][0] * LO_INV + bb0;
            lg[rr * 65 + cc + 1]       = accM[mt][nt][1] + accC[mt][nt][1] * LO_INV + bb1;
            lg[(rr + 8) * 65 + cc]     = accM[mt][nt][2] + accC[mt][nt][2] * LO_INV + bb0;
            lg[(rr + 8) * 65 + cc + 1] = accM[mt][nt][3] + accC[mt][nt][3] * LO_INV + bb1;
        }
    }
    __syncthreads();

    // ---- per-row routing: threads 0..127 own one row each ----
    float e_red = 0.0f;
    if (tid < 128) {
        float l[64];
#pragma unroll
        for (int j = 0; j < 64; j++) l[j] = lg[tid * 65 + j];

        float b1v = l[0], b2v = -3.4e38f;
        int i1 = 0, i2 = 0;
#pragma unroll
        for (int j = 1; j < 64; j++) {
            const float v = l[j];
            if (v > b1v)      { b2v = b1v; i2 = i1; b1v = v; i1 = j; }
            else if (v > b2v) { b2v = v; i2 = j; }
        }
        const float e2 = __expf((b2v - b1v) / TEMP);
        const float w0 = 1.0f / (1.0f + e2);
        const float w1v = e2 / (1.0f + e2);

        float S = 0.0f;
#pragma unroll
        for (int j = 0; j < 64; j++) S += expf(l[j] - b1v);
        const float invS = 1.0f / S;
        float ent = 0.0f;
#pragma unroll
        for (int j = 0; j < 64; j++) {
            const float p = expf(l[j] - b1v) * invS;
            ent -= p * logf(p + 1e-10f);
        }

        const int r = m0 + tid;
        out[2 * r + 0] = w0;
        out[2 * r + 1] = w1v;
        out[2 * B_ROWS + 2 * r + 0] = (float)i1;
        out[2 * B_ROWS + 2 * r + 1] = (float)i2;

        float e = ent;
#pragma unroll
        for (int o = 16; o > 0; o >>= 1) e += __shfl_down_sync(0xffffffffu, e, o);
        e_red = e;
    }
    __syncthreads();
    float* part = lg + 128 * 65;
    if (tid < 128 && (tid & 31) == 0) part[tid >> 5] = e_red;
    __syncthreads();
    if (tid == 0) g_part[blockIdx.x] = part[0] + part[1] + part[2] + part[3];
}

// ---------------- finalize: deterministic mean entropy ----------------
__global__ void fin_kernel(float* __restrict__ out) {
    if (threadIdx.x == 0) {
        float s = 0.0f;
        for (int i = 0; i < B_ROWS / 128; i++) s += g_part[i];
        out[2 * B_ROWS * 2] = (s / (float)B_ROWS) / logf((float)E_DIM);
    }
}

// ---------------- launch ----------------
extern "C" void kernel_launch(void* const* d_in, const int* in_sizes, int n_in,
                              void* d_out, int out_size) {
    const float* x  = (const float*)d_in[0];
    const float* W1 = (const float*)d_in[1];
    const float* b1 = (const float*)d_in[2];
    const float* W2 = (const float*)d_in[3];
    const float* b2 = (const float*)d_in[4];
    float* out = (float*)d_out;
    (void)in_sizes; (void)n_in; (void)out_size;

    cudaFuncSetAttribute(g1_kernel, cudaFuncAttributeMaxDynamicSharedMemorySize, G1_SMEM);
    cudaFuncSetAttribute(g2_kernel, cudaFuncAttributeMaxDynamicSharedMemorySize, G2_SMEM);

    __half *xh, *xl, *w1h, *w1l, *w2h, *w2l;
    cudaGetSymbolAddress((void**)&xh,  g_xh);
    cudaGetSymbolAddress((void**)&xl,  g_xl);
    cudaGetSymbolAddress((void**)&w1h, g_w1h);
    cudaGetSymbolAddress((void**)&w1l, g_w1l);
    cudaGetSymbolAddress((void**)&w2h, g_w2h);
    cudaGetSymbolAddress((void**)&w2l, g_w2l);

    split_kernel<<<4096, 256>>>(x,  xh,  xl,  (B_ROWS * D_DIM) / 4);
    split_kernel<<<2048, 256>>>(W1, w1h, w1l, (H_DIM * D_DIM) / 4);
    split_kernel<<<64,   256>>>(W2, w2h, w2l, (E_DIM * H_DIM) / 4);

    g1_kernel<<<(B_ROWS / 128) * (H_DIM / 64), 256, G1_SMEM>>>(b1);  // 4096 CTAs
    g2_kernel<<<B_ROWS / 128, 256, G2_SMEM>>>(b2, out);              // 128 CTAs
    fin_kernel<<<1, 32>>>(out);
}